// round 11
// baseline (speedup 1.0000x reference)
#include <cuda_runtime.h>

typedef unsigned long long u64;

#define NUM_HEADS 16
#define BATCH     2
#define SEQ       4096
#define DMODEL    1024
#define HD        64

// ---- scratch (device globals: no allocation anywhere) ----
__device__ float g_q[BATCH * NUM_HEADS * SEQ * HD];      // [B,H,S,hd]
__device__ float g_k[BATCH * NUM_HEADS * SEQ * HD];
__device__ float g_v[BATCH * NUM_HEADS * SEQ * HD];
__device__ float g_attn[BATCH * SEQ * DMODEL];           // [B,S,D]

// ---- packed fp32x2 helpers (Blackwell FFMA2: only reachable via PTX) ----
__device__ __forceinline__ void ffma2(u64 &d, u64 a, u64 b) {
    asm("fma.rn.f32x2 %0, %1, %2, %0;" : "+l"(d) : "l"(a), "l"(b));
}
__device__ __forceinline__ u64 fmul2(u64 a, u64 b) {
    u64 d; asm("mul.rn.f32x2 %0, %1, %2;" : "=l"(d) : "l"(a), "l"(b)); return d;
}
__device__ __forceinline__ u64 pack2(float x) {
    u64 d; asm("mov.b64 %0, {%1, %1};" : "=l"(d) : "f"(x)); return d;
}
__device__ __forceinline__ float2 unpk(u64 v) {
    float2 f; asm("mov.b64 {%0, %1}, %2;" : "=f"(f.x), "=f"(f.y) : "l"(v)); return f;
}
__device__ __forceinline__ float ex2f(float x) {
    float y; asm("ex2.approx.f32 %0, %1;" : "=f"(y) : "f"(x)); return y;
}

// =====================================================================
// GEMM: C[M,N] = A[M,K] * W[N,K]^T  (both K-contiguous), K = DMODEL.
// 128x128x16 tile, 256 threads, 8x8 frag via f32x2 pairs along N.
// A stored DUPLICATED+transposed in smem: As[k][2m] = (A[m][k], A[m][k]).
// =====================================================================
#define GBM 128
#define GBN 128
#define GBK 16
#define APITCH 260
#define BPITCH 132
#define GSMEM ((2 * GBK * APITCH + 2 * GBK * BPITCH) * 4)

__device__ __forceinline__ void g_store_tile(
    float* as, float* bs, int lrow, int lcol,
    const float4& pa0, const float4& pa1, const float4& pb0, const float4& pb1)
{
    const float* a0 = (const float*)&pa0;
    const float* a1 = (const float*)&pa1;
    const float* b0 = (const float*)&pb0;
    const float* b1 = (const float*)&pb1;
#pragma unroll
    for (int i = 0; i < 4; i++) {
        *(float2*)&as[(lcol + i) * APITCH + 2 * lrow]        = make_float2(a0[i], a0[i]);
        *(float2*)&as[(lcol + i) * APITCH + 2 * (lrow + 64)] = make_float2(a1[i], a1[i]);
        bs[(lcol + i) * BPITCH + lrow]      = b0[i];
        bs[(lcol + i) * BPITCH + lrow + 64] = b1[i];
    }
}

template<int QKV>
__global__ void __launch_bounds__(256, 1) gemm_nt(
    const float* __restrict__ A,
    const float* __restrict__ W0, const float* __restrict__ W1, const float* __restrict__ W2,
    float* __restrict__ O0, float* __restrict__ O1, float* __restrict__ O2p)
{
    extern __shared__ float smem_g[];
    float* As = smem_g;                       // [2][GBK][APITCH]
    float* Bs = smem_g + 2 * GBK * APITCH;    // [2][GBK][BPITCH]

    const int tid = threadIdx.x;
    const int tx = tid & 15, ty = tid >> 4;
    const int bn = blockIdx.x, bm = blockIdx.y;

    const float* W = W0; float* Out = O0;
    if (QKV) {
        int z = blockIdx.z;
        if (z == 1)      { W = W1; Out = O1;  }
        else if (z == 2) { W = W2; Out = O2p; }
    }

    const int lrow = tid >> 2;          // 0..63
    const int lcol = (tid & 3) << 2;    // 0,4,8,12

    const float* Ag = A + (u64)(bm * GBM + lrow) * DMODEL + lcol;
    const float* Wg = W + (u64)(bn * GBN + lrow) * DMODEL + lcol;

    u64 acc[8][4];
#pragma unroll
    for (int i = 0; i < 8; i++)
#pragma unroll
        for (int j = 0; j < 4; j++) acc[i][j] = 0ull;

    float4 pa0 = *(const float4*)(Ag);
    float4 pa1 = *(const float4*)(Ag + 64 * DMODEL);
    float4 pb0 = *(const float4*)(Wg);
    float4 pb1 = *(const float4*)(Wg + 64 * DMODEL);
    g_store_tile(As, Bs, lrow, lcol, pa0, pa1, pb0, pb1);
    __syncthreads();

    const int NT = DMODEL / GBK;   // 64
#pragma unroll 1
    for (int kt = 0; kt < NT; kt++) {
        if (kt + 1 < NT) {
            const float* Ap = Ag + (kt + 1) * GBK;
            const float* Wp = Wg + (kt + 1) * GBK;
            pa0 = *(const float4*)(Ap);
            pa1 = *(const float4*)(Ap + 64 * DMODEL);
            pb0 = *(const float4*)(Wp);
            pb1 = *(const float4*)(Wp + 64 * DMODEL);
        }
        const float* as = As + (kt & 1) * (GBK * APITCH) + ty * 16;
        const float* bs = Bs + (kt & 1) * (GBK * BPITCH) + tx * 8;
#pragma unroll
        for (int k = 0; k < GBK; k++) {
            ulonglong2 a01 = *(const ulonglong2*)(as + k * APITCH);
            ulonglong2 a23 = *(const ulonglong2*)(as + k * APITCH + 4);
            ulonglong2 a45 = *(const ulonglong2*)(as + k * APITCH + 8);
            ulonglong2 a67 = *(const ulonglong2*)(as + k * APITCH + 12);
            ulonglong2 b01 = *(const ulonglong2*)(bs + k * BPITCH);
            ulonglong2 b23 = *(const ulonglong2*)(bs + k * BPITCH + 4);
            u64 av[8] = {a01.x, a01.y, a23.x, a23.y, a45.x, a45.y, a67.x, a67.y};
            u64 bv[4] = {b01.x, b01.y, b23.x, b23.y};
#pragma unroll
            for (int mi = 0; mi < 8; mi++)
#pragma unroll
                for (int nj = 0; nj < 4; nj++)
                    ffma2(acc[mi][nj], av[mi], bv[nj]);
        }
        if (kt + 1 < NT)
            g_store_tile(As + ((kt + 1) & 1) * (GBK * APITCH),
                         Bs + ((kt + 1) & 1) * (GBK * BPITCH),
                         lrow, lcol, pa0, pa1, pb0, pb1);
        __syncthreads();
    }

    const int mg0 = bm * GBM + ty * 8;
    const int ng0 = bn * GBN + tx * 8;
#pragma unroll
    for (int mi = 0; mi < 8; mi++) {
        float2 c0 = unpk(acc[mi][0]);
        float2 c1 = unpk(acc[mi][1]);
        float2 c2 = unpk(acc[mi][2]);
        float2 c3 = unpk(acc[mi][3]);
        float4 lo = make_float4(c0.x, c0.y, c1.x, c1.y);
        float4 hi = make_float4(c2.x, c2.y, c3.x, c3.y);
        int m = mg0 + mi;
        if (QKV) {
            int b = m >> 12, s = m & (SEQ - 1);
            int h = ng0 >> 6, d = ng0 & 63;
            float* p = Out + (u64)(((b * NUM_HEADS + h) * SEQ + s)) * HD + d;
            *(float4*)p = lo;
            *(float4*)(p + 4) = hi;
        } else {
            float* p = Out + (u64)m * DMODEL + ng0;
            *(float4*)p = lo;
            *(float4*)(p + 4) = hi;
        }
    }
}

// =====================================================================
// Causal flash attention, fp32 f32x2.
// Per CTA: 128 q-rows of one (b,h); kv tiles of 64 rows; only the two
// diagonal tiles are masked. Thread grid 16x16, frags 8(m) x 4(cols).
// =====================================================================
#define QPITCH 260   // Qs[d][2m]  duplicated, scaled
#define KPITCH 68    // Ks[d][n]
#define VPITCH 68    // Vs[j][c]
#define PPITCH 130   // Ps[m][2*col(j)], col(j)=tx+16*(j&3) -> stride-2 STS
#define ASMEM ((64 * QPITCH + 64 * KPITCH + 64 * VPITCH + 128 * PPITCH) * 4)

__global__ void __launch_bounds__(256, 1) attn_kernel(
    const float* __restrict__ Q,
    const float* __restrict__ K,
    const float* __restrict__ V,
    float* __restrict__ O)
{
    extern __shared__ float sm[];
    float* Qs = sm;                       // 64 x QPITCH
    float* Ks = Qs + 64 * QPITCH;         // 64 x KPITCH
    float* Vs = Ks + 64 * KPITCH;         // 64 x VPITCH
    float* Ps = Vs + 64 * VPITCH;         // 128 x PPITCH

    const int tid = threadIdx.x;
    const int tx = tid & 15, ty = tid >> 4;
    const int qi = blockIdx.x;            // 0..31
    const int bh = blockIdx.y;            // 0..31 (b*16+h)
    const int q0 = qi * 128;

    const float* Qbh = Q + (u64)bh * SEQ * HD;
    const float* Kbh = K + (u64)bh * SEQ * HD;
    const float* Vbh = V + (u64)bh * SEQ * HD;

    const float QSCALE = 0.125f * 1.4426950408889634f;  // 1/sqrt(64)*log2(e)

    // q-tile: scaled + transposed + duplicated -> Qs[d][2m]
#pragma unroll
    for (int kk = 0; kk < 8; kk++) {
        int it = tid + kk * 256;
        int r = it >> 4;
        int c4 = (it & 15) << 2;
        float4 v = *(const float4*)(Qbh + (q0 + r) * HD + c4);
        *(float2*)&Qs[(c4 + 0) * QPITCH + 2 * r] = make_float2(v.x * QSCALE, v.x * QSCALE);
        *(float2*)&Qs[(c4 + 1) * QPITCH + 2 * r] = make_float2(v.y * QSCALE, v.y * QSCALE);
        *(float2*)&Qs[(c4 + 2) * QPITCH + 2 * r] = make_float2(v.z * QSCALE, v.z * QSCALE);
        *(float2*)&Qs[(c4 + 3) * QPITCH + 2 * r] = make_float2(v.w * QSCALE, v.w * QSCALE);
    }

    u64 o2[8][2];
    float m_i[8], l_i[8];
#pragma unroll
    for (int i = 0; i < 8; i++) {
        o2[i][0] = 0ull; o2[i][1] = 0ull;
        m_i[i] = -1e30f; l_i[i] = 0.f;
    }

    const int NJ = 2 * qi + 2;
    for (int jt = 0; jt < NJ; jt++) {
        const int j0 = jt * 64;

        // K transposed -> Ks[d][n];  V direct -> Vs[j][c]
#pragma unroll
        for (int kk = 0; kk < 4; kk++) {
            int it = tid + kk * 256;
            int r = it >> 4;
            int c4 = (it & 15) << 2;
            float4 kv = *(const float4*)(Kbh + (j0 + r) * HD + c4);
            Ks[(c4 + 0) * KPITCH + r] = kv.x;
            Ks[(c4 + 1) * KPITCH + r] = kv.y;
            Ks[(c4 + 2) * KPITCH + r] = kv.z;
            Ks[(c4 + 3) * KPITCH + r] = kv.w;
            float4 vv = *(const float4*)(Vbh + (j0 + r) * HD + c4);
            *(float4*)&Vs[r * VPITCH + c4] = vv;
        }
        __syncthreads();

        // GEMM1: S[m][n] = sum_d Qs[d][m] * Ks[d][n]
        u64 s2[8][2];
#pragma unroll
        for (int i = 0; i < 8; i++) { s2[i][0] = 0ull; s2[i][1] = 0ull; }
        const float* qb = Qs + ty * 16;
        const float* kb = Ks + tx * 4;
#pragma unroll 8
        for (int d = 0; d < 64; d++) {
            ulonglong2 a01 = *(const ulonglong2*)(qb + d * QPITCH);
            ulonglong2 a23 = *(const ulonglong2*)(qb + d * QPITCH + 4);
            ulonglong2 a45 = *(const ulonglong2*)(qb + d * QPITCH + 8);
            ulonglong2 a67 = *(const ulonglong2*)(qb + d * QPITCH + 12);
            ulonglong2 bb  = *(const ulonglong2*)(kb + d * KPITCH);
            u64 av[8] = {a01.x, a01.y, a23.x, a23.y, a45.x, a45.y, a67.x, a67.y};
#pragma unroll
            for (int mi = 0; mi < 8; mi++) {
                ffma2(s2[mi][0], av[mi], bb.x);
                ffma2(s2[mi][1], av[mi], bb.y);
            }
        }

        float s[8][4];
#pragma unroll
        for (int mi = 0; mi < 8; mi++) {
            float2 p0 = unpk(s2[mi][0]);
            float2 p1 = unpk(s2[mi][1]);
            s[mi][0] = p0.x; s[mi][1] = p0.y; s[mi][2] = p1.x; s[mi][3] = p1.y;
        }

        // causal mask (diagonal tiles only)
        if (jt >= 2 * qi) {
#pragma unroll
            for (int mi = 0; mi < 8; mi++) {
                int rg = q0 + ty * 8 + mi;
#pragma unroll
                for (int c = 0; c < 4; c++) {
                    int cg = j0 + tx * 4 + c;
                    if (cg > rg) s[mi][c] = -1e30f;
                }
            }
        }

        // online softmax, base-2; rows are 16-lane groups (bfly shuffles)
#pragma unroll
        for (int mi = 0; mi < 8; mi++) {
            float mx = fmaxf(fmaxf(s[mi][0], s[mi][1]), fmaxf(s[mi][2], s[mi][3]));
            mx = fmaxf(mx, __shfl_xor_sync(0xffffffffu, mx, 1));
            mx = fmaxf(mx, __shfl_xor_sync(0xffffffffu, mx, 2));
            mx = fmaxf(mx, __shfl_xor_sync(0xffffffffu, mx, 4));
            mx = fmaxf(mx, __shfl_xor_sync(0xffffffffu, mx, 8));
            float mn = fmaxf(m_i[mi], mx);
            float alpha = ex2f(m_i[mi] - mn);
            float rs = 0.f;
#pragma unroll
            for (int c = 0; c < 4; c++) {
                float p = ex2f(s[mi][c] - mn);
                s[mi][c] = p;
                rs += p;
            }
            rs += __shfl_xor_sync(0xffffffffu, rs, 1);
            rs += __shfl_xor_sync(0xffffffffu, rs, 2);
            rs += __shfl_xor_sync(0xffffffffu, rs, 4);
            rs += __shfl_xor_sync(0xffffffffu, rs, 8);
            l_i[mi] = l_i[mi] * alpha + rs;
            m_i[mi] = mn;
            u64 a2 = pack2(alpha);
            o2[mi][0] = fmul2(o2[mi][0], a2);
            o2[mi][1] = fmul2(o2[mi][1], a2);
        }

        // store P duplicated: j = tx*4+c  ->  col = tx + 16*c
#pragma unroll
        for (int mi = 0; mi < 8; mi++) {
            float* pr = Ps + (ty * 8 + mi) * PPITCH;
#pragma unroll
            for (int c = 0; c < 4; c++) {
                *(float2*)&pr[2 * (tx + 16 * c)] = make_float2(s[mi][c], s[mi][c]);
            }
        }
        __syncthreads();

        // GEMM2: O[m][c] += sum_j P[m][j] * Vs[j][c]
        const float* vb = Vs + tx * 4;
        const float* pbase = Ps + (ty * 8) * PPITCH;
#pragma unroll 4
        for (int jj = 0; jj < 64; jj++) {
            int col2 = 2 * ((jj >> 2) + 16 * (jj & 3));
            const float* pc = pbase + col2;
            ulonglong2 bb = *(const ulonglong2*)(vb + jj * VPITCH);
            u64 av[8];
#pragma unroll
            for (int mi = 0; mi < 8; mi++) av[mi] = *(const u64*)(pc + mi * PPITCH);
#pragma unroll
            for (int mi = 0; mi < 8; mi++) {
                ffma2(o2[mi][0], av[mi], bb.x);
                ffma2(o2[mi][1], av[mi], bb.y);
            }
        }
        __syncthreads();   // protect Ks/Vs/Ps for next tile
    }

    // epilogue: O /= l, write [B,S,D] slice
    const int b = bh >> 4, h = bh & 15;
#pragma unroll
    for (int mi = 0; mi < 8; mi++) {
        float inv = 1.0f / l_i[mi];
        u64 iv = pack2(inv);
        float2 c0 = unpk(fmul2(o2[mi][0], iv));
        float2 c1 = unpk(fmul2(o2[mi][1], iv));
        int rg = q0 + ty * 8 + mi;
        float* p = O + (u64)(b * SEQ + rg) * DMODEL + h * HD + tx * 4;
        *(float4*)p = make_float4(c0.x, c0.y, c1.x, c1.y);
    }
}

// =====================================================================
extern "C" void kernel_launch(void* const* d_in, const int* in_sizes, int n_in,
                              void* d_out, int out_size)
{
    (void)in_sizes; (void)n_in; (void)out_size;
    const float* X  = (const float*)d_in[0];
    const float* Wq = (const float*)d_in[1];
    const float* Wk = (const float*)d_in[2];
    const float* Wv = (const float*)d_in[3];
    const float* Wo = (const float*)d_in[4];
    float* out = (float*)d_out;

    float *gq, *gk, *gv, *ga;
    cudaGetSymbolAddress((void**)&gq, g_q);
    cudaGetSymbolAddress((void**)&gk, g_k);
    cudaGetSymbolAddress((void**)&gv, g_v);
    cudaGetSymbolAddress((void**)&ga, g_attn);

    cudaFuncSetAttribute(gemm_nt<1>, cudaFuncAttributeMaxDynamicSharedMemorySize, GSMEM);
    cudaFuncSetAttribute(gemm_nt<0>, cudaFuncAttributeMaxDynamicSharedMemorySize, GSMEM);
    cudaFuncSetAttribute(attn_kernel, cudaFuncAttributeMaxDynamicSharedMemorySize, ASMEM);

    const int M = BATCH * SEQ;  // 8192

    // 1) Q/K/V projections (+ head-split scatter)
    gemm_nt<1><<<dim3(DMODEL / GBN, M / GBM, 3), 256, GSMEM>>>(
        X, Wq, Wk, Wv, gq, gk, gv);

    // 2) causal flash attention -> g_attn [B,S,D]
    attn_kernel<<<dim3(SEQ / 128, BATCH * NUM_HEADS), 256, ASMEM>>>(gq, gk, gv, ga);

    // 3) output projection -> d_out
    gemm_nt<0><<<dim3(DMODEL / GBN, M / GBM, 1), 256, GSMEM>>>(
        ga, Wo, nullptr, nullptr, out, nullptr, nullptr);
}

// round 12
// speedup vs baseline: 1.3036x; 1.3036x over previous
#include <cuda_runtime.h>

typedef unsigned int u32;
typedef unsigned long long u64;

#define NUM_HEADS 16
#define BATCH     2
#define SEQ       4096
#define DMODEL    1024
#define HD        64

// ---- scratch (device globals: no allocation anywhere) ----
__device__ float g_q[BATCH * NUM_HEADS * SEQ * HD];      // [B,H,S,hd]
__device__ float g_k[BATCH * NUM_HEADS * SEQ * HD];
__device__ float g_v[BATCH * NUM_HEADS * SEQ * HD];
__device__ float g_attn[BATCH * SEQ * DMODEL];           // [B,S,D]

// ---- helpers ----
__device__ __forceinline__ u32 tf32r(float x) {
    u32 r; asm("cvt.rna.tf32.f32 %0, %1;" : "=r"(r) : "f"(x)); return r;
}
__device__ __forceinline__ float ex2f(float x) {
    float y; asm("ex2.approx.f32 %0, %1;" : "=f"(y) : "f"(x)); return y;
}
// D += A(16x8 tf32) * B(8x8 tf32), fp32 accum
__device__ __forceinline__ void mma8(float* d, const u32* a, const u32* b) {
    asm("mma.sync.aligned.m16n8k8.row.col.f32.tf32.tf32.f32 "
        "{%0,%1,%2,%3}, {%4,%5,%6,%7}, {%8,%9}, {%0,%1,%2,%3};"
        : "+f"(d[0]), "+f"(d[1]), "+f"(d[2]), "+f"(d[3])
        : "r"(a[0]), "r"(a[1]), "r"(a[2]), "r"(a[3]), "r"(b[0]), "r"(b[1]));
}
__device__ __forceinline__ uint4 hi4(const float4& v) {
    uint4 h; h.x = tf32r(v.x); h.y = tf32r(v.y); h.z = tf32r(v.z); h.w = tf32r(v.w);
    return h;
}
__device__ __forceinline__ uint4 lo4(const float4& v, const uint4& h) {
    uint4 l;
    l.x = tf32r(v.x - __uint_as_float(h.x));
    l.y = tf32r(v.y - __uint_as_float(h.y));
    l.z = tf32r(v.z - __uint_as_float(h.z));
    l.w = tf32r(v.w - __uint_as_float(h.w));
    return l;
}

// =====================================================================
// GEMM: C[M,N] = A[M,K] * W[N,K]^T, K=1024, via m16n8k8 tf32 MMA.
// CTA tile 128x128, KB=16 double-buffered, 8 warps (2Mx4N), warp 64x32.
// THREE=1: 3xTF32 (hi/lo split of both operands) for fp32-level accuracy.
// QKV=1: epilogue scatters to [B,H,S,hd].
// =====================================================================
#define AP 20   // smem pitch for 16-wide k-tiles (bank-conflict-free frag reads)
#define TILE_U32 (128 * AP)
#define GSM1 (4 * TILE_U32 * 4)   // single: Ah[2] + Bh[2]
#define GSM3 (8 * TILE_U32 * 4)   // three:  + Al[2] + Bl[2]

template<int QKV, int THREE>
__global__ void __launch_bounds__(256, 1) gemm_tf32(
    const float* __restrict__ A, const float* __restrict__ W, float* __restrict__ Out)
{
    extern __shared__ u32 sh[];
    u32* Ah = sh;                    // [2][128][AP]
    u32* Bh = Ah + 2 * TILE_U32;
    u32* Al = Bh + 2 * TILE_U32;     // THREE only
    u32* Bl = Al + 2 * TILE_U32;

    const int tid  = threadIdx.x;
    const int lane = tid & 31, wid = tid >> 5;
    const int g = lane >> 2, t = lane & 3;
    const int wm = wid >> 2, wn = wid & 3;
    const int bm = blockIdx.y, bn = blockIdx.x;

    const int sr = tid >> 2;          // staging row 0..63
    const int sc = (tid & 3) << 2;    // staging col 0,4,8,12

    const float* Ag = A + (u64)(bm * 128 + sr) * DMODEL + sc;
    const float* Wg = W + (u64)(bn * 128 + sr) * DMODEL + sc;

    float acc[4][4][4];
#pragma unroll
    for (int i = 0; i < 4; i++)
#pragma unroll
        for (int j = 0; j < 4; j++)
#pragma unroll
            for (int c = 0; c < 4; c++) acc[i][j][c] = 0.f;

    // ---- stage k-tile 0 ----
    {
        float4 a0 = *(const float4*)(Ag);
        float4 a1 = *(const float4*)(Ag + 64 * DMODEL);
        float4 w0 = *(const float4*)(Wg);
        float4 w1 = *(const float4*)(Wg + 64 * DMODEL);
        uint4 h;
        h = hi4(a0); *(uint4*)&Ah[sr * AP + sc] = h;
        if (THREE) *(uint4*)&Al[sr * AP + sc] = lo4(a0, h);
        h = hi4(a1); *(uint4*)&Ah[(sr + 64) * AP + sc] = h;
        if (THREE) *(uint4*)&Al[(sr + 64) * AP + sc] = lo4(a1, h);
        h = hi4(w0); *(uint4*)&Bh[sr * AP + sc] = h;
        if (THREE) *(uint4*)&Bl[sr * AP + sc] = lo4(w0, h);
        h = hi4(w1); *(uint4*)&Bh[(sr + 64) * AP + sc] = h;
        if (THREE) *(uint4*)&Bl[(sr + 64) * AP + sc] = lo4(w1, h);
    }
    __syncthreads();

    const int NT = DMODEL / 16;   // 64
#pragma unroll 1
    for (int kt = 0; kt < NT; kt++) {
        float4 pa0, pa1, pw0, pw1;
        if (kt + 1 < NT) {
            const float* Ap = Ag + (kt + 1) * 16;
            const float* Wp = Wg + (kt + 1) * 16;
            pa0 = *(const float4*)(Ap);
            pa1 = *(const float4*)(Ap + 64 * DMODEL);
            pw0 = *(const float4*)(Wp);
            pw1 = *(const float4*)(Wp + 64 * DMODEL);
        }
        const int base = (kt & 1) * TILE_U32;
#pragma unroll
        for (int k8 = 0; k8 < 2; k8++) {
            const int co = k8 * 8 + t;
            u32 ah[4][4], al[4][4];
#pragma unroll
            for (int mf = 0; mf < 4; mf++) {
                int r0 = wm * 64 + mf * 16 + g;
                ah[mf][0] = Ah[base + r0 * AP + co];
                ah[mf][1] = Ah[base + (r0 + 8) * AP + co];
                ah[mf][2] = Ah[base + r0 * AP + co + 4];
                ah[mf][3] = Ah[base + (r0 + 8) * AP + co + 4];
                if (THREE) {
                    al[mf][0] = Al[base + r0 * AP + co];
                    al[mf][1] = Al[base + (r0 + 8) * AP + co];
                    al[mf][2] = Al[base + r0 * AP + co + 4];
                    al[mf][3] = Al[base + (r0 + 8) * AP + co + 4];
                }
            }
            u32 bh[4][2], bl[4][2];
#pragma unroll
            for (int nf = 0; nf < 4; nf++) {
                int rn = wn * 32 + nf * 8 + g;
                bh[nf][0] = Bh[base + rn * AP + co];
                bh[nf][1] = Bh[base + rn * AP + co + 4];
                if (THREE) {
                    bl[nf][0] = Bl[base + rn * AP + co];
                    bl[nf][1] = Bl[base + rn * AP + co + 4];
                }
            }
#pragma unroll
            for (int mf = 0; mf < 4; mf++)
#pragma unroll
                for (int nf = 0; nf < 4; nf++) {
                    mma8(acc[mf][nf], ah[mf], bh[nf]);
                    if (THREE) {
                        mma8(acc[mf][nf], ah[mf], bl[nf]);
                        mma8(acc[mf][nf], al[mf], bh[nf]);
                    }
                }
        }
        if (kt + 1 < NT) {
            const int nb = ((kt + 1) & 1) * TILE_U32;
            uint4 h;
            h = hi4(pa0); *(uint4*)&Ah[nb + sr * AP + sc] = h;
            if (THREE) *(uint4*)&Al[nb + sr * AP + sc] = lo4(pa0, h);
            h = hi4(pa1); *(uint4*)&Ah[nb + (sr + 64) * AP + sc] = h;
            if (THREE) *(uint4*)&Al[nb + (sr + 64) * AP + sc] = lo4(pa1, h);
            h = hi4(pw0); *(uint4*)&Bh[nb + sr * AP + sc] = h;
            if (THREE) *(uint4*)&Bl[nb + sr * AP + sc] = lo4(pw0, h);
            h = hi4(pw1); *(uint4*)&Bh[nb + (sr + 64) * AP + sc] = h;
            if (THREE) *(uint4*)&Bl[nb + (sr + 64) * AP + sc] = lo4(pw1, h);
        }
        __syncthreads();
    }

    // ---- epilogue ----
#pragma unroll
    for (int mf = 0; mf < 4; mf++) {
#pragma unroll
        for (int nf = 0; nf < 4; nf++) {
            int m = bm * 128 + wm * 64 + mf * 16 + g;
            int n = bn * 128 + wn * 32 + nf * 8 + 2 * t;
            float2 v0 = make_float2(acc[mf][nf][0], acc[mf][nf][1]);  // row m
            float2 v1 = make_float2(acc[mf][nf][2], acc[mf][nf][3]);  // row m+8
            if (QKV) {
                int b = m >> 12, h = n >> 6, d = n & 63;
                int s0 = m & (SEQ - 1);
                float* p = Out + (u64)((b * NUM_HEADS + h) * SEQ) * HD + d;
                *(float2*)(p + (u64)s0 * HD)       = v0;
                *(float2*)(p + (u64)(s0 + 8) * HD) = v1;
            } else {
                *(float2*)(Out + (u64)m * DMODEL + n)       = v0;
                *(float2*)(Out + (u64)(m + 8) * DMODEL + n) = v1;
            }
        }
    }
}

// =====================================================================
// Causal flash attention: QK^T in 3xTF32 (score path needs precision),
// softmax fp32, P·V single tf32. CTA: 128 q-rows x one (b,h); kv tiles
// of 64. 8 warps, each warp owns 16 q-rows x full 64 kv-cols (row
// reductions stay inside a quad of lanes -> 2 shuffles).
// =====================================================================
#define QP 68   // pitch of Qh/Ql/Kh/Kl/Ps
#define VP 72   // pitch of Vs (transposed B-frag read hits 32 distinct banks)
#define ASM ((2*128*QP + 2*64*QP + 64*VP + 128*QP) * 4)

__global__ void __launch_bounds__(256, 1) attn_tf32(
    const float* __restrict__ Q,
    const float* __restrict__ K,
    const float* __restrict__ V,
    float* __restrict__ O)
{
    extern __shared__ u32 sh[];
    u32* Qh = sh;                  // [128][QP]
    u32* Ql = Qh + 128 * QP;
    u32* Kh = Ql + 128 * QP;       // [64][QP]
    u32* Kl = Kh + 64 * QP;
    u32* Vs = Kl + 64 * QP;        // [64][VP]  (row j, col d)
    u32* Ps = Vs + 64 * VP;        // [128][QP]

    const int tid  = threadIdx.x;
    const int lane = tid & 31, wid = tid >> 5;
    const int g = lane >> 2, t = lane & 3;
    const int qi = blockIdx.x;     // 0..31
    const int bh = blockIdx.y;     // 0..31
    const int q0 = qi * 128;
    const int r0 = wid * 16 + g;   // this lane's local q-row (and r0+8)

    const float* Qbh = Q + (u64)bh * SEQ * HD;
    const float* Kbh = K + (u64)bh * SEQ * HD;
    const float* Vbh = V + (u64)bh * SEQ * HD;

    const float QSCALE = 0.125f * 1.4426950408889634f;  // 1/sqrt(64) * log2(e)

    // ---- load + scale + split Q ----
#pragma unroll
    for (int kk = 0; kk < 8; kk++) {
        int it = tid + kk * 256;
        int r = it >> 4;
        int c4 = (it & 15) << 2;
        float4 v = *(const float4*)(Qbh + (u64)(q0 + r) * HD + c4);
        v.x *= QSCALE; v.y *= QSCALE; v.z *= QSCALE; v.w *= QSCALE;
        uint4 h = hi4(v);
        *(uint4*)&Qh[r * QP + c4] = h;
        *(uint4*)&Ql[r * QP + c4] = lo4(v, h);
    }

    float of[8][4];
    float m_i[2], l_i[2];
#pragma unroll
    for (int nf = 0; nf < 8; nf++)
#pragma unroll
        for (int c = 0; c < 4; c++) of[nf][c] = 0.f;
    m_i[0] = m_i[1] = -1e30f;
    l_i[0] = l_i[1] = 0.f;

    const int NJ = 2 * qi + 2;
    for (int jt = 0; jt < NJ; jt++) {
        const int j0 = jt * 64;

        // ---- stage K (hi/lo) and V (single tf32) ----
#pragma unroll
        for (int kk = 0; kk < 4; kk++) {
            int it = tid + kk * 256;
            int r = it >> 4;
            int c4 = (it & 15) << 2;
            float4 kv = *(const float4*)(Kbh + (u64)(j0 + r) * HD + c4);
            uint4 h = hi4(kv);
            *(uint4*)&Kh[r * QP + c4] = h;
            *(uint4*)&Kl[r * QP + c4] = lo4(kv, h);
            float4 vv = *(const float4*)(Vbh + (u64)(j0 + r) * HD + c4);
            *(uint4*)&Vs[r * VP + c4] = hi4(vv);
        }
        __syncthreads();

        // ---- GEMM1: S = Q K^T  (3xTF32) ----
        float sf[8][4];
#pragma unroll
        for (int nf = 0; nf < 8; nf++)
#pragma unroll
            for (int c = 0; c < 4; c++) sf[nf][c] = 0.f;

#pragma unroll
        for (int k8 = 0; k8 < 8; k8++) {
            const int co = k8 * 8 + t;
            u32 ah[4], al[4];
            ah[0] = Qh[r0 * QP + co];       ah[1] = Qh[(r0 + 8) * QP + co];
            ah[2] = Qh[r0 * QP + co + 4];   ah[3] = Qh[(r0 + 8) * QP + co + 4];
            al[0] = Ql[r0 * QP + co];       al[1] = Ql[(r0 + 8) * QP + co];
            al[2] = Ql[r0 * QP + co + 4];   al[3] = Ql[(r0 + 8) * QP + co + 4];
#pragma unroll
            for (int nf = 0; nf < 8; nf++) {
                int rn = nf * 8 + g;
                u32 bhh[2] = { Kh[rn * QP + co], Kh[rn * QP + co + 4] };
                u32 bll[2] = { Kl[rn * QP + co], Kl[rn * QP + co + 4] };
                mma8(sf[nf], ah, bhh);
                mma8(sf[nf], ah, bll);
                mma8(sf[nf], al, bhh);
            }
        }

        // ---- causal mask (diagonal tiles only) ----
        if (jt >= 2 * qi) {
            int rg0 = q0 + r0, rg1 = rg0 + 8;
#pragma unroll
            for (int nf = 0; nf < 8; nf++) {
                int c0 = j0 + nf * 8 + 2 * t;
                if (c0     > rg0) sf[nf][0] = -1e30f;
                if (c0 + 1 > rg0) sf[nf][1] = -1e30f;
                if (c0     > rg1) sf[nf][2] = -1e30f;
                if (c0 + 1 > rg1) sf[nf][3] = -1e30f;
            }
        }

        // ---- online softmax (base-2); row spread over 4 quad lanes ----
#pragma unroll
        for (int r = 0; r < 2; r++) {
            float mx = -1e30f;
#pragma unroll
            for (int nf = 0; nf < 8; nf++)
                mx = fmaxf(mx, fmaxf(sf[nf][2 * r], sf[nf][2 * r + 1]));
            mx = fmaxf(mx, __shfl_xor_sync(0xffffffffu, mx, 1));
            mx = fmaxf(mx, __shfl_xor_sync(0xffffffffu, mx, 2));
            float mn = fmaxf(m_i[r], mx);
            float alpha = ex2f(m_i[r] - mn);
            float rs = 0.f;
#pragma unroll
            for (int nf = 0; nf < 8; nf++) {
                float p0 = ex2f(sf[nf][2 * r] - mn);
                float p1 = ex2f(sf[nf][2 * r + 1] - mn);
                sf[nf][2 * r] = p0; sf[nf][2 * r + 1] = p1;
                rs += p0 + p1;
            }
            rs += __shfl_xor_sync(0xffffffffu, rs, 1);
            rs += __shfl_xor_sync(0xffffffffu, rs, 2);
            l_i[r] = l_i[r] * alpha + rs;
            m_i[r] = mn;
#pragma unroll
            for (int nf = 0; nf < 8; nf++) {
                of[nf][2 * r]     *= alpha;
                of[nf][2 * r + 1] *= alpha;
            }
        }

        // ---- P -> smem (tf32), C-frag -> A-frag re-layout via smem ----
#pragma unroll
        for (int nf = 0; nf < 8; nf++) {
            int col = nf * 8 + 2 * t;
            u32 p0 = tf32r(sf[nf][0]), p1 = tf32r(sf[nf][1]);
            u32 p2 = tf32r(sf[nf][2]), p3 = tf32r(sf[nf][3]);
            *(uint2*)&Ps[r0 * QP + col]       = make_uint2(p0, p1);
            *(uint2*)&Ps[(r0 + 8) * QP + col] = make_uint2(p2, p3);
        }
        __syncthreads();

        // ---- GEMM2: O += P V  (single tf32) ----
#pragma unroll
        for (int k8 = 0; k8 < 8; k8++) {
            const int co = k8 * 8 + t;
            u32 pa[4];
            pa[0] = Ps[r0 * QP + co];       pa[1] = Ps[(r0 + 8) * QP + co];
            pa[2] = Ps[r0 * QP + co + 4];   pa[3] = Ps[(r0 + 8) * QP + co + 4];
#pragma unroll
            for (int nf = 0; nf < 8; nf++) {
                u32 vb[2] = { Vs[(k8 * 8 + t) * VP + nf * 8 + g],
                              Vs[(k8 * 8 + t + 4) * VP + nf * 8 + g] };
                mma8(of[nf], pa, vb);
            }
        }
        __syncthreads();   // protect Kh/Kl/Vs/Ps for next tile
    }

    // ---- epilogue: O /= l, write [B,S,D] slice ----
    const int b = bh >> 4, h = bh & 15;
#pragma unroll
    for (int r = 0; r < 2; r++) {
        float inv = 1.0f / l_i[r];
        int row = q0 + r0 + 8 * r;
        float* p = O + (u64)(b * SEQ + row) * DMODEL + h * HD;
#pragma unroll
        for (int nf = 0; nf < 8; nf++) {
            *(float2*)(p + nf * 8 + 2 * t) =
                make_float2(of[nf][2 * r] * inv, of[nf][2 * r + 1] * inv);
        }
    }
}

// =====================================================================
extern "C" void kernel_launch(void* const* d_in, const int* in_sizes, int n_in,
                              void* d_out, int out_size)
{
    (void)in_sizes; (void)n_in; (void)out_size;
    const float* X  = (const float*)d_in[0];
    const float* Wq = (const float*)d_in[1];
    const float* Wk = (const float*)d_in[2];
    const float* Wv = (const float*)d_in[3];
    const float* Wo = (const float*)d_in[4];
    float* out = (float*)d_out;

    float *gq, *gk, *gv, *ga;
    cudaGetSymbolAddress((void**)&gq, g_q);
    cudaGetSymbolAddress((void**)&gk, g_k);
    cudaGetSymbolAddress((void**)&gv, g_v);
    cudaGetSymbolAddress((void**)&ga, g_attn);

    cudaFuncSetAttribute(gemm_tf32<1,1>, cudaFuncAttributeMaxDynamicSharedMemorySize, GSM3);
    cudaFuncSetAttribute(gemm_tf32<1,0>, cudaFuncAttributeMaxDynamicSharedMemorySize, GSM1);
    cudaFuncSetAttribute(gemm_tf32<0,0>, cudaFuncAttributeMaxDynamicSharedMemorySize, GSM1);
    cudaFuncSetAttribute(attn_tf32,      cudaFuncAttributeMaxDynamicSharedMemorySize, ASM);

    dim3 ggrid(DMODEL / 128, (BATCH * SEQ) / 128);   // (8, 64)

    // 1) projections: Q,K in 3xTF32 (score path), V single tf32
    gemm_tf32<1,1><<<ggrid, 256, GSM3>>>(X, Wq, gq);
    gemm_tf32<1,1><<<ggrid, 256, GSM3>>>(X, Wk, gk);
    gemm_tf32<1,0><<<ggrid, 256, GSM1>>>(X, Wv, gv);

    // 2) causal flash attention -> g_attn [B,S,D]
    attn_tf32<<<dim3(SEQ / 128, BATCH * NUM_HEADS), 256, ASM>>>(gq, gk, gv, ga);

    // 3) output projection -> d_out (single tf32)
    gemm_tf32<0,0><<<ggrid, 256, GSM1>>>(ga, Wo, out);
}

// round 13
// speedup vs baseline: 2.0681x; 1.5865x over previous
#include <cuda_runtime.h>

typedef unsigned int u32;
typedef unsigned long long u64;

#define NUM_HEADS 16
#define BATCH     2
#define SEQ       4096
#define DMODEL    1024
#define HD        64

// ---- scratch (device globals: no allocation anywhere) ----
__device__ float g_q[BATCH * NUM_HEADS * SEQ * HD];      // [B,H,S,hd]
__device__ float g_k[BATCH * NUM_HEADS * SEQ * HD];
__device__ float g_v[BATCH * NUM_HEADS * SEQ * HD];
__device__ float g_attn[BATCH * SEQ * DMODEL];           // [B,S,D]

// ---- helpers ----
__device__ __forceinline__ u32 tf32r(float x) {
    u32 r; asm("cvt.rna.tf32.f32 %0, %1;" : "=r"(r) : "f"(x)); return r;
}
__device__ __forceinline__ float ex2f(float x) {
    float y; asm("ex2.approx.f32 %0, %1;" : "=f"(y) : "f"(x)); return y;
}
// D += A(16x8 tf32) * B(8x8 tf32), fp32 accum
__device__ __forceinline__ void mma8(float* d, const u32* a, const u32* b) {
    asm("mma.sync.aligned.m16n8k8.row.col.f32.tf32.tf32.f32 "
        "{%0,%1,%2,%3}, {%4,%5,%6,%7}, {%8,%9}, {%0,%1,%2,%3};"
        : "+f"(d[0]), "+f"(d[1]), "+f"(d[2]), "+f"(d[3])
        : "r"(a[0]), "r"(a[1]), "r"(a[2]), "r"(a[3]), "r"(b[0]), "r"(b[1]));
}
__device__ __forceinline__ uint4 hi4(const float4& v) {
    uint4 h; h.x = tf32r(v.x); h.y = tf32r(v.y); h.z = tf32r(v.z); h.w = tf32r(v.w);
    return h;
}
__device__ __forceinline__ uint4 lo4(const float4& v, const uint4& h) {
    uint4 l;
    l.x = tf32r(v.x - __uint_as_float(h.x));
    l.y = tf32r(v.y - __uint_as_float(h.y));
    l.z = tf32r(v.z - __uint_as_float(h.z));
    l.w = tf32r(v.w - __uint_as_float(h.w));
    return l;
}

// =====================================================================
// GEMM: C[M,N] = A[M,K] * W[N,K]^T, K=1024, via m16n8k8 tf32 MMA.
// CTA tile 128x128, KB=16 double-buffered, 8 warps (2Mx4N), warp 64x32.
// THREE=1: 3xTF32 (hi/lo split of both operands) for fp32-level accuracy.
// QKV=1: epilogue scatters to [B,H,S,hd].  2 CTAs/SM.
// =====================================================================
#define AP 20   // smem pitch (bank-conflict-free frag reads)
#define TILE_U32 (128 * AP)
#define GSM1 (4 * TILE_U32 * 4)   // single: Ah[2] + Bh[2]
#define GSM3 (8 * TILE_U32 * 4)   // three:  + Al[2] + Bl[2]

template<int QKV, int THREE>
__global__ void __launch_bounds__(256, 2) gemm_tf32(
    const float* __restrict__ A, const float* __restrict__ W, float* __restrict__ Out)
{
    extern __shared__ u32 sh[];
    u32* Ah = sh;                    // [2][128][AP]
    u32* Bh = Ah + 2 * TILE_U32;
    u32* Al = Bh + 2 * TILE_U32;     // THREE only
    u32* Bl = Al + 2 * TILE_U32;

    const int tid  = threadIdx.x;
    const int lane = tid & 31, wid = tid >> 5;
    const int g = lane >> 2, t = lane & 3;
    const int wm = wid >> 2, wn = wid & 3;
    const int bm = blockIdx.y, bn = blockIdx.x;

    const int sr = tid >> 2;          // staging row 0..63
    const int sc = (tid & 3) << 2;    // staging col 0,4,8,12

    const float* Ag = A + (u64)(bm * 128 + sr) * DMODEL + sc;
    const float* Wg = W + (u64)(bn * 128 + sr) * DMODEL + sc;

    float acc[4][4][4];
#pragma unroll
    for (int i = 0; i < 4; i++)
#pragma unroll
        for (int j = 0; j < 4; j++)
#pragma unroll
            for (int c = 0; c < 4; c++) acc[i][j][c] = 0.f;

    // ---- stage k-tile 0 ----
    {
        float4 a0 = *(const float4*)(Ag);
        float4 a1 = *(const float4*)(Ag + 64 * DMODEL);
        float4 w0 = *(const float4*)(Wg);
        float4 w1 = *(const float4*)(Wg + 64 * DMODEL);
        uint4 h;
        h = hi4(a0); *(uint4*)&Ah[sr * AP + sc] = h;
        if (THREE) *(uint4*)&Al[sr * AP + sc] = lo4(a0, h);
        h = hi4(a1); *(uint4*)&Ah[(sr + 64) * AP + sc] = h;
        if (THREE) *(uint4*)&Al[(sr + 64) * AP + sc] = lo4(a1, h);
        h = hi4(w0); *(uint4*)&Bh[sr * AP + sc] = h;
        if (THREE) *(uint4*)&Bl[sr * AP + sc] = lo4(w0, h);
        h = hi4(w1); *(uint4*)&Bh[(sr + 64) * AP + sc] = h;
        if (THREE) *(uint4*)&Bl[(sr + 64) * AP + sc] = lo4(w1, h);
    }
    __syncthreads();

    const int NT = DMODEL / 16;   // 64
#pragma unroll 1
    for (int kt = 0; kt < NT; kt++) {
        float4 pa0, pa1, pw0, pw1;
        if (kt + 1 < NT) {
            const float* Ap = Ag + (kt + 1) * 16;
            const float* Wp = Wg + (kt + 1) * 16;
            pa0 = *(const float4*)(Ap);
            pa1 = *(const float4*)(Ap + 64 * DMODEL);
            pw0 = *(const float4*)(Wp);
            pw1 = *(const float4*)(Wp + 64 * DMODEL);
        }
        const int base = (kt & 1) * TILE_U32;
#pragma unroll
        for (int k8 = 0; k8 < 2; k8++) {
            const int co = k8 * 8 + t;
            u32 ah[4][4], al[4][4];
#pragma unroll
            for (int mf = 0; mf < 4; mf++) {
                int r0 = wm * 64 + mf * 16 + g;
                ah[mf][0] = Ah[base + r0 * AP + co];
                ah[mf][1] = Ah[base + (r0 + 8) * AP + co];
                ah[mf][2] = Ah[base + r0 * AP + co + 4];
                ah[mf][3] = Ah[base + (r0 + 8) * AP + co + 4];
                if (THREE) {
                    al[mf][0] = Al[base + r0 * AP + co];
                    al[mf][1] = Al[base + (r0 + 8) * AP + co];
                    al[mf][2] = Al[base + r0 * AP + co + 4];
                    al[mf][3] = Al[base + (r0 + 8) * AP + co + 4];
                }
            }
            u32 bh[4][2], bl[4][2];
#pragma unroll
            for (int nf = 0; nf < 4; nf++) {
                int rn = wn * 32 + nf * 8 + g;
                bh[nf][0] = Bh[base + rn * AP + co];
                bh[nf][1] = Bh[base + rn * AP + co + 4];
                if (THREE) {
                    bl[nf][0] = Bl[base + rn * AP + co];
                    bl[nf][1] = Bl[base + rn * AP + co + 4];
                }
            }
#pragma unroll
            for (int mf = 0; mf < 4; mf++)
#pragma unroll
                for (int nf = 0; nf < 4; nf++) {
                    mma8(acc[mf][nf], ah[mf], bh[nf]);
                    if (THREE) {
                        mma8(acc[mf][nf], ah[mf], bl[nf]);
                        mma8(acc[mf][nf], al[mf], bh[nf]);
                    }
                }
        }
        if (kt + 1 < NT) {
            const int nb = ((kt + 1) & 1) * TILE_U32;
            uint4 h;
            h = hi4(pa0); *(uint4*)&Ah[nb + sr * AP + sc] = h;
            if (THREE) *(uint4*)&Al[nb + sr * AP + sc] = lo4(pa0, h);
            h = hi4(pa1); *(uint4*)&Ah[nb + (sr + 64) * AP + sc] = h;
            if (THREE) *(uint4*)&Al[nb + (sr + 64) * AP + sc] = lo4(pa1, h);
            h = hi4(pw0); *(uint4*)&Bh[nb + sr * AP + sc] = h;
            if (THREE) *(uint4*)&Bl[nb + sr * AP + sc] = lo4(pw0, h);
            h = hi4(pw1); *(uint4*)&Bh[nb + (sr + 64) * AP + sc] = h;
            if (THREE) *(uint4*)&Bl[nb + (sr + 64) * AP + sc] = lo4(pw1, h);
        }
        __syncthreads();
    }

    // ---- epilogue ----
#pragma unroll
    for (int mf = 0; mf < 4; mf++) {
#pragma unroll
        for (int nf = 0; nf < 4; nf++) {
            int m = bm * 128 + wm * 64 + mf * 16 + g;
            int n = bn * 128 + wn * 32 + nf * 8 + 2 * t;
            float2 v0 = make_float2(acc[mf][nf][0], acc[mf][nf][1]);  // row m
            float2 v1 = make_float2(acc[mf][nf][2], acc[mf][nf][3]);  // row m+8
            if (QKV) {
                int b = m >> 12, h = n >> 6, d = n & 63;
                int s0 = m & (SEQ - 1);
                float* p = Out + (u64)((b * NUM_HEADS + h) * SEQ) * HD + d;
                *(float2*)(p + (u64)s0 * HD)       = v0;
                *(float2*)(p + (u64)(s0 + 8) * HD) = v1;
            } else {
                *(float2*)(Out + (u64)m * DMODEL + n)       = v0;
                *(float2*)(Out + (u64)(m + 8) * DMODEL + n) = v1;
            }
        }
    }
}

// =====================================================================
// Causal flash attention: QK^T 3xTF32, softmax fp32, P·V tf32.
// Smem diet vs R12: P relayout via register shuffles (no Ps smem),
// Q-lo plane lives in 32 persistent registers -> 88KB smem, 2 CTAs/SM.
// CTA: 128 q-rows x one (b,h); kv tiles of 64; 8 warps x (16 rows, 64 cols).
// =====================================================================
#define QP 68   // pitch of Qh/Kh/Kl (4g+t bank pattern: conflict-free)
#define VP 72   // pitch of Vs (8t+8nf+g pattern: conflict-free)
#define ATSM ((128 * QP + 2 * 64 * QP + 64 * VP) * 4)   // 88064 B

__global__ void __launch_bounds__(256, 2) attn_tf32(
    const float* __restrict__ Q,
    const float* __restrict__ K,
    const float* __restrict__ V,
    float* __restrict__ O)
{
    extern __shared__ u32 sh[];
    u32* Qh = sh;                  // [128][QP]
    u32* Kh = Qh + 128 * QP;       // [64][QP]
    u32* Kl = Kh + 64 * QP;        // [64][QP]
    u32* Vs = Kl + 64 * QP;        // [64][VP]
    u32* Qltmp = Kh;               // Q-lo staging reuses K region (same size)

    const int tid  = threadIdx.x;
    const int lane = tid & 31, wid = tid >> 5;
    const int g = lane >> 2, t = lane & 3;
    const int qi = (gridDim.x - 1) - blockIdx.x;   // longest-work CTAs first
    const int bh = blockIdx.y;     // 0..31
    const int q0 = qi * 128;
    const int r0 = wid * 16 + g;   // lane's local q-rows: r0, r0+8

    const float* Qbh = Q + (u64)bh * SEQ * HD;
    const float* Kbh = K + (u64)bh * SEQ * HD;
    const float* Vbh = V + (u64)bh * SEQ * HD;

    const float QSCALE = 0.125f * 1.4426950408889634f;  // 1/sqrt(64) * log2(e)

    // ---- load + scale + split Q (lo plane staged through K region) ----
#pragma unroll
    for (int kk = 0; kk < 8; kk++) {
        int it = tid + kk * 256;
        int r = it >> 4;
        int c4 = (it & 15) << 2;
        float4 v = *(const float4*)(Qbh + (u64)(q0 + r) * HD + c4);
        v.x *= QSCALE; v.y *= QSCALE; v.z *= QSCALE; v.w *= QSCALE;
        uint4 h = hi4(v);
        *(uint4*)&Qh[r * QP + c4] = h;
        *(uint4*)&Qltmp[r * QP + c4] = lo4(v, h);
    }
    __syncthreads();

    // Q-lo A-fragments -> persistent registers
    u32 ql[8][4];
#pragma unroll
    for (int k8 = 0; k8 < 8; k8++) {
        const int co = k8 * 8 + t;
        ql[k8][0] = Qltmp[r0 * QP + co];
        ql[k8][1] = Qltmp[(r0 + 8) * QP + co];
        ql[k8][2] = Qltmp[r0 * QP + co + 4];
        ql[k8][3] = Qltmp[(r0 + 8) * QP + co + 4];
    }
    __syncthreads();   // before K staging overwrites Qltmp

    float of[8][4];
    float m_i[2], l_i[2];
#pragma unroll
    for (int nf = 0; nf < 8; nf++)
#pragma unroll
        for (int c = 0; c < 4; c++) of[nf][c] = 0.f;
    m_i[0] = m_i[1] = -1e30f;
    l_i[0] = l_i[1] = 0.f;

    const int NJ = 2 * qi + 2;
    for (int jt = 0; jt < NJ; jt++) {
        const int j0 = jt * 64;

        // ---- stage K (hi/lo) and V (single tf32) ----
#pragma unroll
        for (int kk = 0; kk < 4; kk++) {
            int it = tid + kk * 256;
            int r = it >> 4;
            int c4 = (it & 15) << 2;
            float4 kv = *(const float4*)(Kbh + (u64)(j0 + r) * HD + c4);
            uint4 h = hi4(kv);
            *(uint4*)&Kh[r * QP + c4] = h;
            *(uint4*)&Kl[r * QP + c4] = lo4(kv, h);
            float4 vv = *(const float4*)(Vbh + (u64)(j0 + r) * HD + c4);
            *(uint4*)&Vs[r * VP + c4] = hi4(vv);
        }
        __syncthreads();

        // ---- GEMM1: S = Q K^T  (3xTF32) ----
        float sf[8][4];
#pragma unroll
        for (int nf = 0; nf < 8; nf++)
#pragma unroll
            for (int c = 0; c < 4; c++) sf[nf][c] = 0.f;

#pragma unroll
        for (int k8 = 0; k8 < 8; k8++) {
            const int co = k8 * 8 + t;
            u32 ah[4];
            ah[0] = Qh[r0 * QP + co];       ah[1] = Qh[(r0 + 8) * QP + co];
            ah[2] = Qh[r0 * QP + co + 4];   ah[3] = Qh[(r0 + 8) * QP + co + 4];
#pragma unroll
            for (int nf = 0; nf < 8; nf++) {
                int rn = nf * 8 + g;
                u32 bhh[2] = { Kh[rn * QP + co], Kh[rn * QP + co + 4] };
                u32 bll[2] = { Kl[rn * QP + co], Kl[rn * QP + co + 4] };
                mma8(sf[nf], ah, bhh);
                mma8(sf[nf], ah, bll);
                mma8(sf[nf], ql[k8], bhh);
            }
        }

        // ---- causal mask (diagonal tiles only) ----
        if (jt >= 2 * qi) {
            int rg0 = q0 + r0, rg1 = rg0 + 8;
#pragma unroll
            for (int nf = 0; nf < 8; nf++) {
                int c0 = j0 + nf * 8 + 2 * t;
                if (c0     > rg0) sf[nf][0] = -1e30f;
                if (c0 + 1 > rg0) sf[nf][1] = -1e30f;
                if (c0     > rg1) sf[nf][2] = -1e30f;
                if (c0 + 1 > rg1) sf[nf][3] = -1e30f;
            }
        }

        // ---- online softmax (base-2); rows live in a quad -> 2 shuffles ----
#pragma unroll
        for (int r = 0; r < 2; r++) {
            float mx = -1e30f;
#pragma unroll
            for (int nf = 0; nf < 8; nf++)
                mx = fmaxf(mx, fmaxf(sf[nf][2 * r], sf[nf][2 * r + 1]));
            mx = fmaxf(mx, __shfl_xor_sync(0xffffffffu, mx, 1));
            mx = fmaxf(mx, __shfl_xor_sync(0xffffffffu, mx, 2));
            float mn = fmaxf(m_i[r], mx);
            float alpha = ex2f(m_i[r] - mn);
            float rs = 0.f;
#pragma unroll
            for (int nf = 0; nf < 8; nf++) {
                float p0 = ex2f(sf[nf][2 * r] - mn);
                float p1 = ex2f(sf[nf][2 * r + 1] - mn);
                sf[nf][2 * r] = p0; sf[nf][2 * r + 1] = p1;
                rs += p0 + p1;
            }
            rs += __shfl_xor_sync(0xffffffffu, rs, 1);
            rs += __shfl_xor_sync(0xffffffffu, rs, 2);
            l_i[r] = l_i[r] * alpha + rs;
            m_i[r] = mn;
#pragma unroll
            for (int nf = 0; nf < 8; nf++) {
                of[nf][2 * r]     *= alpha;
                of[nf][2 * r + 1] *= alpha;
            }
        }

        // ---- P: tf32 convert, then C-frag -> A-frag via warp shuffles ----
        u32 pt[8][4];
#pragma unroll
        for (int nf = 0; nf < 8; nf++)
#pragma unroll
            for (int c = 0; c < 4; c++) pt[nf][c] = tf32r(sf[nf][c]);

        const int srcA = (lane & 28) | (t >> 1);   // g*4 + t/2

        // ---- GEMM2: O += P V  (single tf32) ----
#pragma unroll
        for (int k8 = 0; k8 < 8; k8++) {
            u32 pa[4], v0, v1;
            v0 = __shfl_sync(0xffffffffu, pt[k8][0], srcA);
            v1 = __shfl_sync(0xffffffffu, pt[k8][1], srcA);
            pa[0] = (t & 1) ? v1 : v0;
            v0 = __shfl_sync(0xffffffffu, pt[k8][2], srcA);
            v1 = __shfl_sync(0xffffffffu, pt[k8][3], srcA);
            pa[1] = (t & 1) ? v1 : v0;
            v0 = __shfl_sync(0xffffffffu, pt[k8][0], srcA + 2);
            v1 = __shfl_sync(0xffffffffu, pt[k8][1], srcA + 2);
            pa[2] = (t & 1) ? v1 : v0;
            v0 = __shfl_sync(0xffffffffu, pt[k8][2], srcA + 2);
            v1 = __shfl_sync(0xffffffffu, pt[k8][3], srcA + 2);
            pa[3] = (t & 1) ? v1 : v0;
#pragma unroll
            for (int nf = 0; nf < 8; nf++) {
                u32 vb[2] = { Vs[(k8 * 8 + t) * VP + nf * 8 + g],
                              Vs[(k8 * 8 + t + 4) * VP + nf * 8 + g] };
                mma8(of[nf], pa, vb);
            }
        }
        __syncthreads();   // protect Kh/Kl/Vs for next tile's staging
    }

    // ---- epilogue: O /= l, write [B,S,D] slice ----
    const int b = bh >> 4, h = bh & 15;
#pragma unroll
    for (int r = 0; r < 2; r++) {
        float inv = 1.0f / l_i[r];
        int row = q0 + r0 + 8 * r;
        float* p = O + (u64)(b * SEQ + row) * DMODEL + h * HD;
#pragma unroll
        for (int nf = 0; nf < 8; nf++) {
            *(float2*)(p + nf * 8 + 2 * t) =
                make_float2(of[nf][2 * r] * inv, of[nf][2 * r + 1] * inv);
        }
    }
}

// =====================================================================
extern "C" void kernel_launch(void* const* d_in, const int* in_sizes, int n_in,
                              void* d_out, int out_size)
{
    (void)in_sizes; (void)n_in; (void)out_size;
    const float* X  = (const float*)d_in[0];
    const float* Wq = (const float*)d_in[1];
    const float* Wk = (const float*)d_in[2];
    const float* Wv = (const float*)d_in[3];
    const float* Wo = (const float*)d_in[4];
    float* out = (float*)d_out;

    float *gq, *gk, *gv, *ga;
    cudaGetSymbolAddress((void**)&gq, g_q);
    cudaGetSymbolAddress((void**)&gk, g_k);
    cudaGetSymbolAddress((void**)&gv, g_v);
    cudaGetSymbolAddress((void**)&ga, g_attn);

    cudaFuncSetAttribute(gemm_tf32<1,1>, cudaFuncAttributeMaxDynamicSharedMemorySize, GSM3);
    cudaFuncSetAttribute(gemm_tf32<1,0>, cudaFuncAttributeMaxDynamicSharedMemorySize, GSM1);
    cudaFuncSetAttribute(gemm_tf32<0,0>, cudaFuncAttributeMaxDynamicSharedMemorySize, GSM1);
    cudaFuncSetAttribute(attn_tf32,      cudaFuncAttributeMaxDynamicSharedMemorySize, ATSM);

    dim3 ggrid(DMODEL / 128, (BATCH * SEQ) / 128);   // (8, 64)

    // 1) projections: Q,K in 3xTF32 (score path), V single tf32
    gemm_tf32<1,1><<<ggrid, 256, GSM3>>>(X, Wq, gq);
    gemm_tf32<1,1><<<ggrid, 256, GSM3>>>(X, Wk, gk);
    gemm_tf32<1,0><<<ggrid, 256, GSM1>>>(X, Wv, gv);

    // 2) causal flash attention -> g_attn [B,S,D]
    attn_tf32<<<dim3(SEQ / 128, BATCH * NUM_HEADS), 256, ATSM>>>(gq, gk, gv, ga);

    // 3) output projection -> d_out (single tf32)
    gemm_tf32<0,0><<<ggrid, 256, GSM1>>>(ga, Wo, out);
}